// round 2
// baseline (speedup 1.0000x reference)
#include <cuda_runtime.h>
#include <math.h>

#define BB 32
#define CC 64
#define HH 128
#define WW 128
#define HW (HH*WW)          // 16384
#define HW4 (HW/4)          // 4096
#define C_R 38
#define C_IR 26
#define BN_EPS 1e-5f

// Scratch (device globals; no allocation allowed)
__device__ float4 g_stats[BB*HW];   // (r_avg, r_max, ir_avg, ir_max) per pixel
__device__ float  g_A1[BB*HW];
__device__ float  g_A2[BB*HW];
__device__ unsigned long long g_mask[BB];

// ---------------------------------------------------------------------------
// Kernel 1: per-batch top-k (k=38) channel mask from M[b,c].
// Rank rule matches jax.lax.top_k: larger value first, ties -> smaller index.
// ---------------------------------------------------------------------------
__global__ void topk_mask_kernel(const float* __restrict__ M) {
    int b = blockIdx.x;
    int c = threadIdx.x;
    __shared__ float m[CC];
    __shared__ unsigned wbal[2];
    m[c] = M[b * CC + c];
    __syncthreads();
    float mv = m[c];
    int rank = 0;
#pragma unroll
    for (int j = 0; j < CC; j++) {
        float mj = m[j];
        rank += (mj > mv) || (mj == mv && j < c);
    }
    unsigned bal = __ballot_sync(0xffffffffu, rank < C_R);
    if ((c & 31) == 0) wbal[c >> 5] = bal;
    __syncthreads();
    if (c == 0)
        g_mask[b] = (unsigned long long)wbal[0] |
                    ((unsigned long long)wbal[1] << 32);
}

// ---------------------------------------------------------------------------
// Kernel 2: channel reduction. Each thread: 4 consecutive pixels, 64 channels.
// Writes interleaved stats (r_avg, r_max, ir_avg, ir_max) per pixel.
// Max init 0.0f is exact: the reference maxes over mask*x where the opposite
// partition contributes zeros, and both partitions are non-empty (38/26).
// ---------------------------------------------------------------------------
__global__ void stats_kernel(const float* __restrict__ x) {
    int t = blockIdx.x * blockDim.x + threadIdx.x;   // 0 .. B*HW4-1
    int b = t >> 12;                                  // / HW4
    int p = t & (HW4 - 1);
    unsigned long long m = g_mask[b];
    const float4* xb = (const float4*)x + (size_t)b * CC * HW4 + p;

    float4 rs = make_float4(0.f,0.f,0.f,0.f), is = rs;
    float4 rm = rs, im = rs;

#pragma unroll 8
    for (int c = 0; c < CC; c++) {
        float4 v = __ldg(xb + c * HW4);
        bool rel = (m >> c) & 1ull;
        if (rel) {
            rs.x += v.x; rs.y += v.y; rs.z += v.z; rs.w += v.w;
            rm.x = fmaxf(rm.x, v.x); rm.y = fmaxf(rm.y, v.y);
            rm.z = fmaxf(rm.z, v.z); rm.w = fmaxf(rm.w, v.w);
        } else {
            is.x += v.x; is.y += v.y; is.z += v.z; is.w += v.w;
            im.x = fmaxf(im.x, v.x); im.y = fmaxf(im.y, v.y);
            im.z = fmaxf(im.z, v.z); im.w = fmaxf(im.w, v.w);
        }
    }
    const float inv_r  = 1.0f / (float)C_R;
    const float inv_ir = 1.0f / (float)C_IR;
    int pix = (t << 2);          // first of this thread's 4 pixels (global idx)
    g_stats[pix + 0] = make_float4(rs.x*inv_r, rm.x, is.x*inv_ir, im.x);
    g_stats[pix + 1] = make_float4(rs.y*inv_r, rm.y, is.y*inv_ir, im.y);
    g_stats[pix + 2] = make_float4(rs.z*inv_r, rm.z, is.z*inv_ir, im.z);
    g_stats[pix + 3] = make_float4(rs.w*inv_r, rm.w, is.w*inv_ir, im.w);
}

// ---------------------------------------------------------------------------
// Kernel 3: 7x7 conv (pad 3, cross-correlation) + BN + relu + sigmoid on the
// two 2-channel stat maps -> gate planes A1, A2. 16x16 output tile, 22x22 halo.
// Stats are interleaved: one float4 load per halo pixel.
// ---------------------------------------------------------------------------
__global__ void conv_gate_kernel(const float* __restrict__ w,
                                 const float* __restrict__ gamma,
                                 const float* __restrict__ beta,
                                 const float* __restrict__ mean,
                                 const float* __restrict__ var) {
    __shared__ float4 s[22][23];
    __shared__ float sw[98];
    __shared__ float sbn[2];

    int b  = blockIdx.z;
    int ty0 = blockIdx.y * 16, tx0 = blockIdx.x * 16;
    int tid = threadIdx.y * 16 + threadIdx.x;

    if (tid < 98) sw[tid] = w[tid];
    if (tid == 98) {
        float sc = rsqrtf(var[0] + BN_EPS) * gamma[0];
        sbn[0] = sc;
        sbn[1] = beta[0] - mean[0] * sc;
    }
    int base = b * HW;
    const float4 zero4 = make_float4(0.f,0.f,0.f,0.f);
    for (int i = tid; i < 22 * 22; i += 256) {
        int ly = i / 22, lx = i - ly * 22;
        int gy = ty0 + ly - 3, gx = tx0 + lx - 3;
        bool ok = (gy >= 0) & (gy < HH) & (gx >= 0) & (gx < WW);
        s[ly][lx] = ok ? g_stats[base + gy * WW + gx] : zero4;
    }
    __syncthreads();

    int ty = threadIdx.y, tx = threadIdx.x;
    float a1 = 0.f, a2 = 0.f;
#pragma unroll
    for (int ky = 0; ky < 7; ky++) {
#pragma unroll
        for (int kx = 0; kx < 7; kx++) {
            float w0 = sw[ky * 7 + kx];
            float w1 = sw[49 + ky * 7 + kx];
            float4 v = s[ty + ky][tx + kx];
            a1 += w0 * v.x + w1 * v.y;
            a2 += w0 * v.z + w1 * v.w;
        }
    }
    float sc = sbn[0], sh = sbn[1];
    a1 = fmaxf(a1 * sc + sh, 0.f);
    a2 = fmaxf(a2 * sc + sh, 0.f);
    a1 = 1.f / (1.f + expf(-a1));
    a2 = 1.f / (1.f + expf(-a2));

    int o = base + (ty0 + ty) * WW + (tx0 + tx);
    g_A1[o] = a1;
    g_A2[o] = a2;
}

// ---------------------------------------------------------------------------
// Kernel 4: out[b,c,h,w] = x[b,c,h,w] * (maskbit(b,c) ? A1[b,h,w] : A2[b,h,w])
// (relevant*A1 + irelevant*A2 collapses to this since masks are complementary)
// ---------------------------------------------------------------------------
__global__ void apply_kernel(const float* __restrict__ x,
                             float* __restrict__ out) {
    int t = blockIdx.x * blockDim.x + threadIdx.x;   // 0 .. B*C*HW4-1
    int p  = t & (HW4 - 1);
    int bc = t >> 12;
    int b  = bc >> 6;
    int c  = bc & 63;
    bool rel = (g_mask[b] >> c) & 1ull;
    const float4* Ap = (const float4*)(rel ? g_A1 : g_A2) + b * HW4 + p;
    float4 a = __ldg(Ap);
    float4 v = ((const float4*)x)[t];
    float4 o;
    o.x = v.x * a.x; o.y = v.y * a.y; o.z = v.z * a.z; o.w = v.w * a.w;
    ((float4*)out)[t] = o;
}

// ---------------------------------------------------------------------------
extern "C" void kernel_launch(void* const* d_in, const int* in_sizes, int n_in,
                              void* d_out, int out_size) {
    const float* x      = (const float*)d_in[0];
    const float* M      = (const float*)d_in[1];
    const float* conv_w = (const float*)d_in[2];
    const float* gamma  = (const float*)d_in[3];
    const float* beta   = (const float*)d_in[4];
    const float* mean   = (const float*)d_in[5];
    const float* var    = (const float*)d_in[6];
    float* out = (float*)d_out;

    topk_mask_kernel<<<BB, CC>>>(M);

    {
        int threads = 256;
        int total = BB * HW4;                 // 131072
        stats_kernel<<<total / threads, threads>>>(x);
    }

    {
        dim3 blk(16, 16);
        dim3 grd(WW / 16, HH / 16, BB);
        conv_gate_kernel<<<grd, blk>>>(conv_w, gamma, beta, mean, var);
    }

    {
        int threads = 256;
        int total = BB * CC * HW4;            // 8388608
        apply_kernel<<<total / threads, threads>>>(x, out);
    }
}